// round 10
// baseline (speedup 1.0000x reference)
#include <cuda_runtime.h>

#define D       128
#define MMAX    65536
#define QMAX    32
#define NEG_INF_F (-1e30f)
#define MARGIN  0.1f
#define NBLK_C  256

// ---------------- scratch (no allocation allowed: device globals) ----------
__device__ float    g_sims[(size_t)MMAX * QMAX];   // [row][q], 8 MB
__device__ unsigned g_pos_table[65536];            // bit q: id in pidxs[q]
__device__ unsigned g_neg_table[65536];            // bit q: id in nnegs[q]
__device__ int      g_maxp[QMAX];                  // encoded float max (pos-masked)
__device__ int      g_maxn[QMAX];                  // encoded float max (neg-masked)
__device__ float    g_part[(size_t)NBLK_C * QMAX * 5];

// order-preserving float <-> int encoding (works for negatives, atomicMax-able)
__device__ __forceinline__ int encf(float f) {
    int i = __float_as_int(f);
    return i >= 0 ? i : i ^ 0x7FFFFFFF;
}
__device__ __forceinline__ float decf(int i) {
    return __int_as_float(i >= 0 ? i : i ^ 0x7FFFFFFF);
}

// ---------------- kernel 0: zero id tables ---------------------------------
__global__ void k_zero_tables() {
    int stride = gridDim.x * blockDim.x;
    for (int i = blockIdx.x * blockDim.x + threadIdx.x; i < 65536; i += stride) {
        g_pos_table[i] = 0u;
        g_neg_table[i] = 0u;
    }
}

// ---------------- kernel 1: build tables + init maxima ---------------------
__global__ void k_setup(const long long* __restrict__ targets_col,
                        const long long* __restrict__ qidxs,
                        const long long* __restrict__ pidxs,
                        const long long* __restrict__ nnegs,
                        int Q, int P, int Nn, int triplet_len) {
    __shared__ int jloc[QMAX];
    int tid = threadIdx.x;
    if (tid < Q) {
        long long qid = targets_col[(long long)tid * triplet_len];
        int j = 0;                       // argmax-of-all-false default = 0
        for (int k = 0; k < Q; k++) {
            if (qidxs[k] == qid) { j = k; break; }
        }
        jloc[tid] = j;
        g_maxp[tid] = encf(NEG_INF_F);
        g_maxn[tid] = encf(NEG_INF_F);
    }
    __syncthreads();
    for (int i = tid; i < Q * P; i += blockDim.x) {
        int q = i / P, p = i % P;
        int id = ((int)pidxs[(long long)jloc[q] * P + p]) & 0xFFFF;
        atomicOr(&g_pos_table[id], 1u << q);
    }
    for (int i = tid; i < Q * Nn; i += blockDim.x) {
        int q = i / Nn, p = i % Nn;
        int id = ((int)nnegs[(long long)jloc[q] * Nn + p]) & 0xFFFF;
        atomicOr(&g_neg_table[id], 1u << q);
    }
}

// ---------------- kernel 2: sims GEMM + masked maxima -----------------------
// Block tile: 32 queries x 32 rows. 8 warps, each warp owns 4 rows,
// lane == query index. float4 smem loads: 1 q-load + 4 row-broadcasts per k4.
__global__ void __launch_bounds__(256) k_sims(
    const float* __restrict__ col, const float* __restrict__ rows,
    const long long* __restrict__ tgt_row,
    int m, int Q, int triplet_len)
{
    __shared__ float4 sq[32 * 32];  // [k4][q]
    __shared__ float4 sr[32 * 32];  // [r][k4]
    __shared__ int    st[32];
    __shared__ int    smaxp[QMAX], smaxn[QMAX];

    int tid  = threadIdx.x;
    int row0 = blockIdx.x * 32;

    // stage query vectors (coalesced float4)
    for (int i = tid; i < 1024; i += 256) {
        int q = i >> 5, k4 = i & 31;
        float4 v = make_float4(0.f, 0.f, 0.f, 0.f);
        if (q < Q)
            v = reinterpret_cast<const float4*>(col + (size_t)q * triplet_len * D)[k4];
        sq[k4 * 32 + q] = v;
    }
    // stage 32 db rows (coalesced float4)
    for (int i = tid; i < 1024; i += 256) {
        int r = i >> 5, k4 = i & 31;
        float4 v = make_float4(0.f, 0.f, 0.f, 0.f);
        if (row0 + r < m)
            v = reinterpret_cast<const float4*>(rows + (size_t)(row0 + r) * D)[k4];
        sr[r * 32 + k4] = v;
    }
    if (tid < 32) st[tid] = (row0 + tid < m) ? (((int)tgt_row[row0 + tid]) & 0xFFFF) : 0;
    if (tid < QMAX) { smaxp[tid] = encf(NEG_INF_F); smaxn[tid] = encf(NEG_INF_F); }
    __syncthreads();

    int warp = tid >> 5, lane = tid & 31;
    int rbase = warp * 4;

    float acc[4] = {0.f, 0.f, 0.f, 0.f};
#pragma unroll
    for (int k4 = 0; k4 < 32; k4++) {
        float4 qv = sq[k4 * 32 + lane];
#pragma unroll
        for (int r = 0; r < 4; r++) {
            float4 rv = sr[(rbase + r) * 32 + k4];
            acc[r] += qv.x * rv.x + qv.y * rv.y + qv.z * rv.z + qv.w * rv.w;
        }
    }

    if (lane < Q) {
        int mp = encf(NEG_INF_F), mn = encf(NEG_INF_F);
#pragma unroll
        for (int r = 0; r < 4; r++) {
            int rr = row0 + rbase + r;
            if (rr < m) {
                float s = acc[r];
                g_sims[(size_t)rr * QMAX + lane] = s;
                unsigned pos = g_pos_table[st[rbase + r]];
                unsigned neg = g_neg_table[st[rbase + r]];
                int e = encf(s);
                if ((pos >> lane) & 1u)     mp = max(mp, e);
                if (!((neg >> lane) & 1u))  mn = max(mn, e);
            }
        }
        atomicMax(&smaxp[lane], mp);
        atomicMax(&smaxn[lane], mn);
    }
    __syncthreads();
    if (tid < Q) {
        atomicMax(&g_maxp[tid], smaxp[tid]);
        atomicMax(&g_maxn[tid], smaxn[tid]);
    }
}

// ---------------- kernel 3: selection + deterministic partial sums ----------
__global__ void __launch_bounds__(256) k_select(
    const long long* __restrict__ tgt_row, int m, int Q)
{
    __shared__ float red[8][QMAX][5];
    int tid = threadIdx.x, warp = tid >> 5, lane = tid & 31;
    int gw = blockIdx.x * 8 + warp;
    int nw = gridDim.x * 8;

    float thrp = 0.f, thrn = 0.f;
    if (lane < Q) {
        thrp = decf(g_maxn[lane]) + MARGIN;                 // pos_sel: s <  thrp
        thrn = fmaxf(0.4f, decf(g_maxp[lane])) - MARGIN;    // neg_sel: s >  thrn
    }
    float psum = 0.f, pscnt = 0.f, nsum = 0.f, nscnt = 0.f, pmcnt = 0.f;
    for (int row = gw; row < m; row += nw) {
        int t = ((int)tgt_row[row]) & 0xFFFF;
        unsigned pos = g_pos_table[t];
        unsigned neg = g_neg_table[t];
        float s = g_sims[(size_t)row * QMAX + lane];
        if (lane < Q) {
            if ((pos >> lane) & 1u) {
                pmcnt += 1.f;                               // has_pos tracking
                if (s < thrp) { psum += 1.f - s; pscnt += 1.f; }
            }
            if (!((neg >> lane) & 1u) && s > thrn) { nsum += s; nscnt += 1.f; }
        }
    }
    red[warp][lane][0] = psum;  red[warp][lane][1] = pscnt;
    red[warp][lane][2] = nsum;  red[warp][lane][3] = nscnt;
    red[warp][lane][4] = pmcnt;
    __syncthreads();
    if (warp == 0) {
        float a0 = 0.f, a1 = 0.f, a2 = 0.f, a3 = 0.f, a4 = 0.f;
        for (int w = 0; w < 8; w++) {   // fixed order => deterministic
            a0 += red[w][lane][0]; a1 += red[w][lane][1]; a2 += red[w][lane][2];
            a3 += red[w][lane][3]; a4 += red[w][lane][4];
        }
        float* p = &g_part[((size_t)blockIdx.x * QMAX + lane) * 5];
        p[0] = a0; p[1] = a1; p[2] = a2; p[3] = a3; p[4] = a4;
    }
}

// ---------------- kernel 4: final deterministic reduction -------------------
__global__ void k_final(float* __restrict__ out, int Q, int nblk) {
    __shared__ float terms[QMAX];
    int q = threadIdx.x;
    if (q < QMAX) terms[q] = 0.f;
    __syncthreads();
    if (q < Q) {
        float psum = 0.f, pscnt = 0.f, nsum = 0.f, nscnt = 0.f, pmcnt = 0.f;
        for (int b = 0; b < nblk; b++) {   // fixed order => deterministic
            const float* p = &g_part[((size_t)b * QMAX + q) * 5];
            psum += p[0]; pscnt += p[1]; nsum += p[2]; nscnt += p[3]; pmcnt += p[4];
        }
        float pl = (pscnt > 0.f) ? psum / pscnt : 0.f;
        float nl = (nscnt > 0.f) ? nsum / nscnt : 0.f;
        terms[q] = (pmcnt > 0.f) ? (pl + nl) : 0.f;
    }
    __syncthreads();
    if (q == 0) {
        float loss = 0.f;
        for (int i = 0; i < Q; i++) loss += terms[i];
        out[0] = loss / (float)Q;
    }
}

// ---------------- launcher ---------------------------------------------------
extern "C" void kernel_launch(void* const* d_in, const int* in_sizes, int n_in,
                              void* d_out, int out_size) {
    const float*     col   = (const float*)d_in[0];      // inputs_col [n, 128]
    const float*     row   = (const float*)d_in[1];      // inputs_row [m, 128]
    const long long* tcol  = (const long long*)d_in[2];  // targets_col [n]
    const long long* trow  = (const long long*)d_in[3];  // targets_row [m]
    const long long* qidxs = (const long long*)d_in[4];  // [Q]
    const long long* pidxs = (const long long*)d_in[5];  // [Q, P]
    const long long* nnegs = (const long long*)d_in[6];  // [Q, Nn]
    (void)n_in; (void)out_size;

    int n  = in_sizes[2];
    int m  = in_sizes[3];
    int Q  = in_sizes[4];
    int P  = in_sizes[5] / Q;
    int Nn = in_sizes[6] / Q;
    int tl = n / Q;                   // triplet_len = nNeg + 2

    k_zero_tables<<<64, 256>>>();
    k_setup<<<1, 256>>>(tcol, qidxs, pidxs, nnegs, Q, P, Nn, tl);
    k_sims<<<(m + 31) / 32, 256>>>(col, row, trow, m, Q, tl);
    k_select<<<NBLK_C, 256>>>(trow, m, Q);
    k_final<<<1, 32>>>((float*)d_out, Q, NBLK_C);
}

// round 11
// speedup vs baseline: 1.3409x; 1.3409x over previous
#include <cuda_runtime.h>

#define D       128
#define MMAX    65536
#define QMAX    32
#define NEG_INF_F (-1e30f)
#define MARGIN  0.1f
#define NBLK_C  512   // k_select blocks

// ---------------- scratch (device globals; no allocation allowed) ----------
__device__ float    g_sims[(size_t)MMAX * QMAX];   // [row][q], 8 MB
__device__ unsigned g_pos_table[65536];
__device__ unsigned g_neg_table[65536];
__device__ int      g_maxp[QMAX];
__device__ int      g_maxn[QMAX];
__device__ float    g_part[(size_t)NBLK_C * QMAX * 5];

// order-preserving float <-> int encoding (atomicMax-able over negatives)
__device__ __forceinline__ int encf(float f) {
    int i = __float_as_int(f);
    return i >= 0 ? i : i ^ 0x7FFFFFFF;
}
__device__ __forceinline__ float decf(int i) {
    return __int_as_float(i >= 0 ? i : i ^ 0x7FFFFFFF);
}

// packed f32x2 FMA (Blackwell; only reachable via PTX)
__device__ __forceinline__ unsigned long long fma2(
    unsigned long long a, unsigned long long b, unsigned long long c) {
    unsigned long long d;
    asm("fma.rn.f32x2 %0, %1, %2, %3;" : "=l"(d) : "l"(a), "l"(b), "l"(c));
    return d;
}

// ---------------- kernel 0: zero id tables ---------------------------------
__global__ void k_zero_tables() {
    int stride = gridDim.x * blockDim.x;
    for (int i = blockIdx.x * blockDim.x + threadIdx.x; i < 65536; i += stride) {
        g_pos_table[i] = 0u;
        g_neg_table[i] = 0u;
    }
}

// ---------------- kernel 1: build tables + init maxima ---------------------
__global__ void k_setup(const long long* __restrict__ targets_col,
                        const long long* __restrict__ qidxs,
                        const long long* __restrict__ pidxs,
                        const long long* __restrict__ nnegs,
                        int Q, int P, int Nn, int triplet_len) {
    __shared__ int jloc[QMAX];
    int tid = threadIdx.x;
    if (tid < Q) {
        long long qid = targets_col[(long long)tid * triplet_len];
        int j = 0;
        for (int k = 0; k < Q; k++) {
            if (qidxs[k] == qid) { j = k; break; }
        }
        jloc[tid] = j;
        g_maxp[tid] = encf(NEG_INF_F);
        g_maxn[tid] = encf(NEG_INF_F);
    }
    __syncthreads();
    for (int i = tid; i < Q * P; i += blockDim.x) {
        int q = i / P, p = i % P;
        int id = ((int)pidxs[(long long)jloc[q] * P + p]) & 0xFFFF;
        atomicOr(&g_pos_table[id], 1u << q);
    }
    for (int i = tid; i < Q * Nn; i += blockDim.x) {
        int q = i / Nn, p = i % Nn;
        int id = ((int)nnegs[(long long)jloc[q] * Nn + p]) & 0xFFFF;
        atomicOr(&g_neg_table[id], 1u << q);
    }
}

// ---------------- kernel 2: sims GEMM + masked maxima -----------------------
// Tile: 128 rows x 32 queries per block. 8 warps, 16 rows/warp, lane = query.
// f32x2 packed FMA: per k4 step, 1 query LDS.128 + 16 row broadcasts + 32 FMA2.
#define SIMS_ROWS 128
__global__ void __launch_bounds__(256) k_sims(
    const float* __restrict__ col, const float* __restrict__ rows,
    const long long* __restrict__ tgt_row,
    int m, int Q, int triplet_len)
{
    extern __shared__ unsigned long long smem_raw[];
    // carve: sq = 32 k4 x 32 q ulonglong2 (16KB); sr = 128 r x 32 k4 ulonglong2 (64KB)
    ulonglong2* sq = reinterpret_cast<ulonglong2*>(smem_raw);
    ulonglong2* sr = sq + 32 * 32;
    int*  st    = reinterpret_cast<int*>(sr + SIMS_ROWS * 32);
    int*  smaxp = st + SIMS_ROWS;
    int*  smaxn = smaxp + QMAX;

    int tid  = threadIdx.x;
    int row0 = blockIdx.x * SIMS_ROWS;

    // stage query vectors: sq[k4][q]
#pragma unroll
    for (int it = 0; it < 4; it++) {
        int idx = tid + it * 256;           // 1024 items
        int q = idx & 31, k4 = idx >> 5;
        ulonglong2 v = make_ulonglong2(0ull, 0ull);
        if (q < Q)
            v = reinterpret_cast<const ulonglong2*>(
                    col + (size_t)q * triplet_len * D)[k4];
        sq[k4 * 32 + q] = v;
    }
    // stage rows: sr[r][k4], coalesced
#pragma unroll
    for (int it = 0; it < (SIMS_ROWS * 32) / 256; it++) {
        int idx = tid + it * 256;
        int r = idx >> 5, k4 = idx & 31;
        ulonglong2 v = make_ulonglong2(0ull, 0ull);
        if (row0 + r < m)
            v = reinterpret_cast<const ulonglong2*>(
                    rows + (size_t)(row0 + r) * D)[k4];
        sr[r * 32 + k4] = v;
    }
    if (tid < SIMS_ROWS)
        st[tid] = (row0 + tid < m) ? (((int)tgt_row[row0 + tid]) & 0xFFFF) : 0;
    if (tid < QMAX) { smaxp[tid] = encf(NEG_INF_F); smaxn[tid] = encf(NEG_INF_F); }
    __syncthreads();

    int warp = tid >> 5, lane = tid & 31;
    int rbase = warp * 16;

    unsigned long long acc[16];
#pragma unroll
    for (int r = 0; r < 16; r++) acc[r] = 0ull;

#pragma unroll
    for (int k4 = 0; k4 < 32; k4++) {
        ulonglong2 q2 = sq[k4 * 32 + lane];
#pragma unroll
        for (int r = 0; r < 16; r++) {
            ulonglong2 r2 = sr[(rbase + r) * 32 + k4];  // broadcast
            acc[r] = fma2(q2.x, r2.x, acc[r]);
            acc[r] = fma2(q2.y, r2.y, acc[r]);
        }
    }

    if (lane < Q) {
        int mp = encf(NEG_INF_F), mn = encf(NEG_INF_F);
#pragma unroll
        for (int r = 0; r < 16; r++) {
            int rr = row0 + rbase + r;
            if (rr < m) {
                float2 f = *reinterpret_cast<float2*>(&acc[r]);
                float s = f.x + f.y;
                g_sims[(size_t)rr * QMAX + lane] = s;
                unsigned pos = g_pos_table[st[rbase + r]];
                unsigned neg = g_neg_table[st[rbase + r]];
                int e = encf(s);
                if ((pos >> lane) & 1u)     mp = max(mp, e);
                if (!((neg >> lane) & 1u))  mn = max(mn, e);
            }
        }
        atomicMax(&smaxp[lane], mp);
        atomicMax(&smaxn[lane], mn);
    }
    __syncthreads();
    if (tid < Q) {
        atomicMax(&g_maxp[tid], smaxp[tid]);
        atomicMax(&g_maxn[tid], smaxn[tid]);
    }
}

// ---------------- kernel 3: selection + deterministic partial sums ----------
// 512 blocks x 8 warps, 16 contiguous rows per warp, all loads issued up front.
__global__ void __launch_bounds__(256) k_select(
    const long long* __restrict__ tgt_row, int m, int Q)
{
    __shared__ float red[8][QMAX][5];
    int tid = threadIdx.x, warp = tid >> 5, lane = tid & 31;
    int base = (blockIdx.x * 8 + warp) * 16;

    float thrp = 0.f, thrn = 0.f;
    if (lane < Q) {
        thrp = decf(g_maxn[lane]) + MARGIN;               // pos_sel: s <  thrp
        thrn = fmaxf(0.4f, decf(g_maxp[lane])) - MARGIN;  // neg_sel: s >  thrn
    }

    float s[16];
    int   t[16];
#pragma unroll
    for (int i = 0; i < 16; i++) {
        int row = base + i;
        s[i] = (row < m) ? g_sims[(size_t)row * QMAX + lane] : 0.f;
        t[i] = (row < m) ? (((int)tgt_row[row]) & 0xFFFF) : -1;
    }

    float psum = 0.f, pscnt = 0.f, nsum = 0.f, nscnt = 0.f, pmcnt = 0.f;
#pragma unroll
    for (int i = 0; i < 16; i++) {
        if (t[i] < 0) continue;
        unsigned pos = g_pos_table[t[i]];
        unsigned neg = g_neg_table[t[i]];
        if (lane < Q) {
            if ((pos >> lane) & 1u) {
                pmcnt += 1.f;
                if (s[i] < thrp) { psum += 1.f - s[i]; pscnt += 1.f; }
            }
            if (!((neg >> lane) & 1u) && s[i] > thrn) { nsum += s[i]; nscnt += 1.f; }
        }
    }
    red[warp][lane][0] = psum;  red[warp][lane][1] = pscnt;
    red[warp][lane][2] = nsum;  red[warp][lane][3] = nscnt;
    red[warp][lane][4] = pmcnt;
    __syncthreads();
    if (warp == 0) {
        float a0 = 0.f, a1 = 0.f, a2 = 0.f, a3 = 0.f, a4 = 0.f;
#pragma unroll
        for (int w = 0; w < 8; w++) {   // fixed order => deterministic
            a0 += red[w][lane][0]; a1 += red[w][lane][1]; a2 += red[w][lane][2];
            a3 += red[w][lane][3]; a4 += red[w][lane][4];
        }
        float* p = &g_part[((size_t)blockIdx.x * QMAX + lane) * 5];
        p[0] = a0; p[1] = a1; p[2] = a2; p[3] = a3; p[4] = a4;
    }
}

// ---------------- kernel 4: final deterministic reduction -------------------
// 256 threads: 8 chunks x 32 queries; fixed chunk order + fixed combine order.
__global__ void k_final(float* __restrict__ out, int Q, int nblk) {
    __shared__ float red[8][QMAX][5];
    __shared__ float terms[QMAX];
    int tid = threadIdx.x;
    int chunk = tid >> 5, q = tid & 31;
    int per = nblk / 8;

    float a0 = 0.f, a1 = 0.f, a2 = 0.f, a3 = 0.f, a4 = 0.f;
    for (int b = chunk * per; b < (chunk + 1) * per; b++) {  // fixed order
        const float* p = &g_part[((size_t)b * QMAX + q) * 5];
        a0 += p[0]; a1 += p[1]; a2 += p[2]; a3 += p[3]; a4 += p[4];
    }
    red[chunk][q][0] = a0; red[chunk][q][1] = a1; red[chunk][q][2] = a2;
    red[chunk][q][3] = a3; red[chunk][q][4] = a4;
    if (tid < QMAX) terms[tid] = 0.f;
    __syncthreads();

    if (tid < Q) {
        float psum = 0.f, pscnt = 0.f, nsum = 0.f, nscnt = 0.f, pmcnt = 0.f;
#pragma unroll
        for (int c = 0; c < 8; c++) {   // fixed order
            psum += red[c][tid][0]; pscnt += red[c][tid][1];
            nsum += red[c][tid][2]; nscnt += red[c][tid][3];
            pmcnt += red[c][tid][4];
        }
        float pl = (pscnt > 0.f) ? psum / pscnt : 0.f;
        float nl = (nscnt > 0.f) ? nsum / nscnt : 0.f;
        terms[tid] = (pmcnt > 0.f) ? (pl + nl) : 0.f;
    }
    __syncthreads();
    if (tid == 0) {
        float loss = 0.f;
        for (int i = 0; i < Q; i++) loss += terms[i];
        out[0] = loss / (float)Q;
    }
}

// ---------------- launcher ---------------------------------------------------
extern "C" void kernel_launch(void* const* d_in, const int* in_sizes, int n_in,
                              void* d_out, int out_size) {
    const float*     col   = (const float*)d_in[0];      // inputs_col [n, 128]
    const float*     row   = (const float*)d_in[1];      // inputs_row [m, 128]
    const long long* tcol  = (const long long*)d_in[2];  // targets_col [n]
    const long long* trow  = (const long long*)d_in[3];  // targets_row [m]
    const long long* qidxs = (const long long*)d_in[4];  // [Q]
    const long long* pidxs = (const long long*)d_in[5];  // [Q, P]
    const long long* nnegs = (const long long*)d_in[6];  // [Q, Nn]
    (void)n_in; (void)out_size;

    int n  = in_sizes[2];
    int m  = in_sizes[3];
    int Q  = in_sizes[4];
    int P  = in_sizes[5] / Q;
    int Nn = in_sizes[6] / Q;
    int tl = n / Q;                   // triplet_len = nNeg + 2

    // dynamic smem for k_sims: sq 16KB + sr 64KB + st 512B + maxima 256B
    size_t smem_bytes = (32 * 32 + SIMS_ROWS * 32) * sizeof(ulonglong2)
                      + (SIMS_ROWS + 2 * QMAX) * sizeof(int);
    static bool attr_set = false;
    if (!attr_set) {
        cudaFuncSetAttribute(k_sims, cudaFuncAttributeMaxDynamicSharedMemorySize,
                             (int)smem_bytes);
        attr_set = true;
    }

    k_zero_tables<<<128, 512>>>();
    k_setup<<<1, 256>>>(tcol, qidxs, pidxs, nnegs, Q, P, Nn, tl);
    k_sims<<<(m + SIMS_ROWS - 1) / SIMS_ROWS, 256, smem_bytes>>>(col, row, trow, m, Q, tl);
    k_select<<<NBLK_C, 256>>>(trow, m, Q);
    k_final<<<1, 256>>>((float*)d_out, Q, NBLK_C);
}